// round 1
// baseline (speedup 1.0000x reference)
#include <cuda_runtime.h>
#include <math.h>

#define Bc 64
#define Tc 64
#define Hc 1024
#define Vc 32000
#define Ec 512
#define Gc 4096   // 4*H

// ---------------- scratch (static device allocations; no cudaMalloc) ----------
__device__ float g_X [Tc*Bc*Ec];      // embedded inputs, row (t*B+b)
__device__ float g_Z1[Tc*Bc*Gc];      // precomputed x@W1 + b1, row (t*B+b)
__device__ float g_Zt[Bc*Gc];         // per-(step,layer) preactivations
__device__ float g_h [4][Bc*Hc];
__device__ float g_c [4][Bc*Hc];
__device__ float g_H4[Tc*Bc*Hc];      // h4 history, row (t*B+b)

// ---------------- packed fp32x2 helpers --------------------------------------
union F2U { float2 f; unsigned long long u; };

__device__ __forceinline__ void ffma2(unsigned long long& d,
                                      unsigned long long a,
                                      unsigned long long b) {
    asm("fma.rn.f32x2 %0, %1, %2, %0;" : "+l"(d) : "l"(a), "l"(b));
}
__device__ __forceinline__ unsigned long long dup2(float x) {
    F2U t; t.f = make_float2(x, x); return t.u;
}

// ---------------- init / embed ------------------------------------------------
__global__ void k_init(const float* __restrict__ h1, const float* __restrict__ c1,
                       const float* __restrict__ h2, const float* __restrict__ c2,
                       const float* __restrict__ h3, const float* __restrict__ c3,
                       const float* __restrict__ h4, const float* __restrict__ c4,
                       float* __restrict__ ph, float* __restrict__ pc) {
    int i = blockIdx.x * blockDim.x + threadIdx.x;   // 0 .. B*H-1
    ph[0*Bc*Hc + i] = h1[i];  pc[0*Bc*Hc + i] = c1[i];
    ph[1*Bc*Hc + i] = h2[i];  pc[1*Bc*Hc + i] = c2[i];
    ph[2*Bc*Hc + i] = h3[i];  pc[2*Bc*Hc + i] = c3[i];
    ph[3*Bc*Hc + i] = h4[i];  pc[3*Bc*Hc + i] = c4[i];
}

__global__ void k_embed(const int* __restrict__ tgt, const float* __restrict__ emb,
                        float* __restrict__ X) {
    // one float4 per thread over [T*B, E]
    int i = blockIdx.x * blockDim.x + threadIdx.x;   // 0 .. T*B*E/4-1
    int row = i / (Ec/4);
    int e4  = i % (Ec/4);
    int t = row / Bc, b = row % Bc;
    int v = tgt[b*Tc + t];
    ((float4*)X)[i] = ((const float4*)(emb + (size_t)v*Ec))[e4];
}

// ---------------- big GEMM: C = A[M,K] @ W[K,N] + bias ------------------------
// MODE 0: C[m,n] = acc + bias[n]              (Z1 precompute)
// MODE 1: row remap (t*B+b) -> (b*T+t), write logits to d_out  (FC head)
// Tiles: 128x128x16, 256 threads, per-thread 8x8 via packed fp32x2.
template<int MODE>
__global__ void __launch_bounds__(256)
k_gemm(const float* __restrict__ A, const float* __restrict__ W,
       const float* __restrict__ bias, float* __restrict__ C,
       int M, int N, int K)
{
    __shared__ float sA [16][132];    // transposed A tile, padded (132*4 % 16 == 0)
    __shared__ float sBd[16][260];    // B tile with each value DUPLICATED (for fp32x2)

    const int bn  = blockIdx.x * 128;
    const int bm  = blockIdx.y * 128;
    const int tid = threadIdx.x;
    const int tx  = tid & 15, ty = tid >> 4;
    const int m0  = ty * 8,  n0 = tx * 8;

    unsigned long long acc[4][8];
    #pragma unroll
    for (int i = 0; i < 4; i++)
        #pragma unroll
        for (int j = 0; j < 8; j++) acc[i][j] = 0ull;

    for (int k0 = 0; k0 < K; k0 += 16) {
        // load A tile (128 rows x 16 cols) transposed into sA[k][m]
        #pragma unroll
        for (int r = 0; r < 2; r++) {
            int q = tid + r * 256;             // 0..511 float4s
            int row = q >> 2, c4 = (q & 3) * 4;
            float4 v = *(const float4*)(A + (size_t)(bm + row) * K + k0 + c4);
            sA[c4+0][row] = v.x; sA[c4+1][row] = v.y;
            sA[c4+2][row] = v.z; sA[c4+3][row] = v.w;
        }
        // load W tile (16 rows x 128 cols), duplicating each value
        #pragma unroll
        for (int r = 0; r < 2; r++) {
            int q = tid + r * 256;             // 0..511 float4s
            int row = q >> 5, c4 = (q & 31) * 4;
            float4 v = *(const float4*)(W + (size_t)(k0 + row) * N + bn + c4);
            *(unsigned long long*)&sBd[row][(c4+0)*2] = dup2(v.x);
            *(unsigned long long*)&sBd[row][(c4+1)*2] = dup2(v.y);
            *(unsigned long long*)&sBd[row][(c4+2)*2] = dup2(v.z);
            *(unsigned long long*)&sBd[row][(c4+3)*2] = dup2(v.w);
        }
        __syncthreads();

        #pragma unroll 4
        for (int k = 0; k < 16; k++) {
            ulonglong2 a01 = *(const ulonglong2*)&sA[k][m0];
            ulonglong2 a23 = *(const ulonglong2*)&sA[k][m0 + 4];
            unsigned long long am[4] = {a01.x, a01.y, a23.x, a23.y};
            unsigned long long wd[8];
            #pragma unroll
            for (int j = 0; j < 4; j++) {
                ulonglong2 w = *(const ulonglong2*)&sBd[k][n0*2 + j*4];
                wd[2*j] = w.x; wd[2*j+1] = w.y;
            }
            #pragma unroll
            for (int i = 0; i < 4; i++)
                #pragma unroll
                for (int j = 0; j < 8; j++)
                    ffma2(acc[i][j], am[i], wd[j]);
        }
        __syncthreads();
    }

    // epilogue
    #pragma unroll
    for (int i = 0; i < 4; i++) {
        #pragma unroll
        for (int s = 0; s < 2; s++) {
            int m = bm + m0 + 2*i + s;
            float v[8];
            #pragma unroll
            for (int j = 0; j < 8; j++) { F2U t; t.u = acc[i][j]; v[j] = s ? t.f.y : t.f.x; }
            const float* bp = bias + bn + n0;
            float4 o0 = make_float4(v[0]+bp[0], v[1]+bp[1], v[2]+bp[2], v[3]+bp[3]);
            float4 o1 = make_float4(v[4]+bp[4], v[5]+bp[5], v[6]+bp[6], v[7]+bp[7]);
            float* dst;
            if (MODE == 0) {
                dst = C + (size_t)m * N + bn + n0;
            } else {
                int t_ = m >> 6, b_ = m & 63;             // m = t*B+b
                dst = C + (size_t)(b_ * Tc + t_) * N + bn + n0;
            }
            *(float4*)dst       = o0;
            *(float4*)(dst + 4) = o1;
        }
    }
}

// ---------------- recurrence z-GEMM: z[64,4096] = init + A1@W1p + A2@W2p ------
// M=64 fixed, N tile 32 (grid 128), K=1024 per source, 128 threads,
// per-thread 4x4 via packed fp32x2 (pairs over m), BK=64.
__global__ void __launch_bounds__(128)
k_zgemm(const float* __restrict__ zinit, const float* __restrict__ bias,
        const float* __restrict__ A1, const float* __restrict__ W1p,
        const float* __restrict__ A2, const float* __restrict__ W2p,
        float* __restrict__ zout)
{
    __shared__ float sA [64][68];     // transposed A tile [k][m]
    __shared__ float sBd[64][68];     // W tile duplicated [k][2n]

    const int bn  = blockIdx.x * 32;
    const int tid = threadIdx.x;
    const int tx  = tid & 7, ty = tid >> 3;
    const int m0  = ty * 4, n0 = tx * 4;

    unsigned long long acc[2][4];
    #pragma unroll
    for (int i = 0; i < 2; i++)
        #pragma unroll
        for (int j = 0; j < 4; j++) acc[i][j] = 0ull;

    #pragma unroll 1
    for (int src = 0; src < 2; src++) {
        const float* A = src ? A2 : A1;
        const float* W = src ? W2p : W1p;
        if (A == nullptr) continue;
        for (int k0 = 0; k0 < Hc; k0 += 64) {
            // A tile: 64 rows x 64 cols -> 1024 float4, 8 per thread
            #pragma unroll
            for (int r = 0; r < 8; r++) {
                int q = tid + r * 128;
                int row = q >> 4, c4 = (q & 15) * 4;
                float4 v = *(const float4*)(A + (size_t)row * Hc + k0 + c4);
                sA[c4+0][row] = v.x; sA[c4+1][row] = v.y;
                sA[c4+2][row] = v.z; sA[c4+3][row] = v.w;
            }
            // W tile: 64 rows x 32 cols -> 512 float4, 4 per thread, duplicated
            #pragma unroll
            for (int r = 0; r < 4; r++) {
                int q = tid + r * 128;
                int row = q >> 3, c4 = (q & 7) * 4;
                float4 v = *(const float4*)(W + (size_t)(k0 + row) * Gc + bn + c4);
                *(unsigned long long*)&sBd[row][(c4+0)*2] = dup2(v.x);
                *(unsigned long long*)&sBd[row][(c4+1)*2] = dup2(v.y);
                *(unsigned long long*)&sBd[row][(c4+2)*2] = dup2(v.z);
                *(unsigned long long*)&sBd[row][(c4+3)*2] = dup2(v.w);
            }
            __syncthreads();

            #pragma unroll 16
            for (int k = 0; k < 64; k++) {
                ulonglong2 a  = *(const ulonglong2*)&sA[k][m0];
                unsigned long long am[2] = {a.x, a.y};
                ulonglong2 w0 = *(const ulonglong2*)&sBd[k][n0*2];
                ulonglong2 w1 = *(const ulonglong2*)&sBd[k][n0*2 + 4];
                unsigned long long wd[4] = {w0.x, w0.y, w1.x, w1.y};
                #pragma unroll
                for (int i = 0; i < 2; i++)
                    #pragma unroll
                    for (int j = 0; j < 4; j++)
                        ffma2(acc[i][j], am[i], wd[j]);
            }
            __syncthreads();
        }
    }

    // epilogue: add zinit (precomputed x@W1+b1) or bias
    #pragma unroll
    for (int i = 0; i < 2; i++) {
        #pragma unroll
        for (int s = 0; s < 2; s++) {
            int m = m0 + 2*i + s;
            float v[4];
            #pragma unroll
            for (int j = 0; j < 4; j++) { F2U t; t.u = acc[i][j]; v[j] = s ? t.f.y : t.f.x; }
            float4 o;
            if (zinit) {
                float4 zi = *(const float4*)(zinit + (size_t)m * Gc + bn + n0);
                o = make_float4(v[0]+zi.x, v[1]+zi.y, v[2]+zi.z, v[3]+zi.w);
            } else {
                float4 bb = *(const float4*)(bias + bn + n0);
                o = make_float4(v[0]+bb.x, v[1]+bb.y, v[2]+bb.z, v[3]+bb.w);
            }
            *(float4*)(zout + (size_t)m * Gc + bn + n0) = o;
        }
    }
}

// ---------------- LSTM gates --------------------------------------------------
__device__ __forceinline__ float sigm(float x) { return 1.f / (1.f + __expf(-x)); }

__global__ void k_gate(const float* __restrict__ z, float* __restrict__ h,
                       float* __restrict__ c, float* __restrict__ h4row)
{
    int i = blockIdx.x * blockDim.x + threadIdx.x;  // 0 .. B*H-1
    int b = i >> 10, u = i & 1023;
    const float* zr = z + (size_t)b * Gc + u;
    float zi = zr[0], zf = zr[1024], zg = zr[2048], zo = zr[3072];
    float cn = sigm(zf) * c[i] + sigm(zi) * tanhf(zg);
    float hn = sigm(zo) * tanhf(cn);
    c[i] = cn;
    h[i] = hn;
    if (h4row) h4row[i] = hn;
}

// ---------------- row softmax over V=32000, in place in d_out ----------------
__global__ void __launch_bounds__(256) k_softmax(float* __restrict__ out)
{
    const int row = blockIdx.x;
    float* p = out + (size_t)row * Vc;
    const int tid = threadIdx.x;
    __shared__ float red[8];

    float mx = -3.4e38f;
    for (int i = tid; i < Vc; i += 256) mx = fmaxf(mx, p[i]);
    #pragma unroll
    for (int o = 16; o > 0; o >>= 1) mx = fmaxf(mx, __shfl_xor_sync(0xffffffffu, mx, o));
    if ((tid & 31) == 0) red[tid >> 5] = mx;
    __syncthreads();
    mx = red[0];
    #pragma unroll
    for (int j = 1; j < 8; j++) mx = fmaxf(mx, red[j]);

    float sum = 0.f;
    for (int i = tid; i < Vc; i += 256) { float e = __expf(p[i] - mx); p[i] = e; sum += e; }
    #pragma unroll
    for (int o = 16; o > 0; o >>= 1) sum += __shfl_xor_sync(0xffffffffu, sum, o);
    __syncthreads();
    if ((tid & 31) == 0) red[tid >> 5] = sum;
    __syncthreads();
    sum = red[0];
    #pragma unroll
    for (int j = 1; j < 8; j++) sum += red[j];

    float inv = 1.f / sum;
    for (int i = tid; i < Vc; i += 256) p[i] *= inv;
}

// ---------------- launch ------------------------------------------------------
extern "C" void kernel_launch(void* const* d_in, const int* in_sizes, int n_in,
                              void* d_out, int out_size)
{
    const int*   tgt = (const int*)  d_in[0];
    const float* h1  = (const float*)d_in[1],  *c1 = (const float*)d_in[2];
    const float* h2  = (const float*)d_in[3],  *c2 = (const float*)d_in[4];
    const float* h3  = (const float*)d_in[5],  *c3 = (const float*)d_in[6];
    const float* h4  = (const float*)d_in[7],  *c4 = (const float*)d_in[8];
    const float* emb = (const float*)d_in[9];
    const float* W1  = (const float*)d_in[10], *U1 = (const float*)d_in[11], *b1 = (const float*)d_in[12];
    const float* W2  = (const float*)d_in[13], *U2 = (const float*)d_in[14], *b2 = (const float*)d_in[15];
    const float* W3  = (const float*)d_in[16], *U3 = (const float*)d_in[17], *b3 = (const float*)d_in[18];
    const float* W4  = (const float*)d_in[19], *U4 = (const float*)d_in[20], *b4 = (const float*)d_in[21];
    const float* Wfc = (const float*)d_in[22], *bfc = (const float*)d_in[23];
    float* out = (float*)d_out;

    float *pX, *pZ1, *pZt, *phb, *pcb, *pH4;
    cudaGetSymbolAddress((void**)&pX,  g_X);
    cudaGetSymbolAddress((void**)&pZ1, g_Z1);
    cudaGetSymbolAddress((void**)&pZt, g_Zt);
    cudaGetSymbolAddress((void**)&phb, g_h);
    cudaGetSymbolAddress((void**)&pcb, g_c);
    cudaGetSymbolAddress((void**)&pH4, g_H4);
    float* ph[4]; float* pc[4];
    for (int l = 0; l < 4; l++) { ph[l] = phb + (size_t)l * Bc * Hc; pc[l] = pcb + (size_t)l * Bc * Hc; }

    // state init + embedding gather
    k_init <<<Bc*Hc/256, 256>>>(h1, c1, h2, c2, h3, c3, h4, c4, phb, pcb);
    k_embed<<<Tc*Bc*Ec/4/256, 256>>>(tgt, emb, pX);

    // hoisted: Z1 = X @ W1 + b1 for all timesteps  [4096 x 4096, K=512]
    k_gemm<0><<<dim3(Gc/128, (Tc*Bc)/128), 256>>>(pX, W1, b1, pZ1, Tc*Bc, Gc, Ec);

    const float* Wl[4] = {nullptr, W2, W3, W4};
    const float* Ul[4] = {U1, U2, U3, U4};
    const float* bl[4] = {nullptr, b2, b3, b4};

    for (int t = 0; t < Tc; t++) {
        // layer 1: z = Z1[t] + h1 @ U1
        k_zgemm<<<128, 128>>>(pZ1 + (size_t)t * Bc * Gc, nullptr,
                              nullptr, nullptr, ph[0], Ul[0], pZt);
        k_gate<<<Bc*Hc/256, 256>>>(pZt, ph[0], pc[0], nullptr);
        // layers 2..4: z = b + h_{l-1} @ W + h_l @ U
        for (int l = 1; l < 4; l++) {
            k_zgemm<<<128, 128>>>(nullptr, bl[l],
                                  ph[l-1], Wl[l], ph[l], Ul[l], pZt);
            k_gate<<<Bc*Hc/256, 256>>>(pZt, ph[l], pc[l],
                                       (l == 3) ? (pH4 + (size_t)t * Bc * Hc) : nullptr);
        }
    }

    // hoisted FC head: logits (row-remapped to [B,T,V]) then softmax in place
    k_gemm<1><<<dim3(Vc/128, (Tc*Bc)/128), 256>>>(pH4, Wfc, bfc, out, Tc*Bc, Vc, Hc);
    k_softmax<<<Tc*Bc, 256>>>(out);
}

// round 2
// speedup vs baseline: 1.0042x; 1.0042x over previous
#include <cuda_runtime.h>
#include <math.h>

#define Bc 64
#define Tc 64
#define Hc 1024
#define Vc 32000
#define Ec 512
#define Gc 4096   // 4*H

// ---------------- scratch (static device allocations; no cudaMalloc) ----------
__device__ float g_X [Tc*Bc*Ec];      // embedded inputs, row (t*B+b)
__device__ float g_Z1[Tc*Bc*Gc];      // precomputed x@W1 + b1, row (t*B+b)
__device__ float g_Zt[Bc*Gc];         // per-(step,layer) preactivations
__device__ float g_h [4][Bc*Hc];
__device__ float g_c [4][Bc*Hc];
__device__ float g_H4[Tc*Bc*Hc];      // h4 history, row (t*B+b)

// ---------------- packed fp32x2 helpers --------------------------------------
union F2U { float2 f; unsigned long long u; };

__device__ __forceinline__ void ffma2(unsigned long long& d,
                                      unsigned long long a,
                                      unsigned long long b) {
    asm("fma.rn.f32x2 %0, %1, %2, %0;" : "+l"(d) : "l"(a), "l"(b));
}
__device__ __forceinline__ unsigned long long dup2(float x) {
    F2U t; t.f = make_float2(x, x); return t.u;
}

// ---------------- init / embed ------------------------------------------------
__global__ void k_init(const float* __restrict__ h1, const float* __restrict__ c1,
                       const float* __restrict__ h2, const float* __restrict__ c2,
                       const float* __restrict__ h3, const float* __restrict__ c3,
                       const float* __restrict__ h4, const float* __restrict__ c4,
                       float* __restrict__ ph, float* __restrict__ pc) {
    int i = blockIdx.x * blockDim.x + threadIdx.x;   // 0 .. B*H-1
    ph[0*Bc*Hc + i] = h1[i];  pc[0*Bc*Hc + i] = c1[i];
    ph[1*Bc*Hc + i] = h2[i];  pc[1*Bc*Hc + i] = c2[i];
    ph[2*Bc*Hc + i] = h3[i];  pc[2*Bc*Hc + i] = c3[i];
    ph[3*Bc*Hc + i] = h4[i];  pc[3*Bc*Hc + i] = c4[i];
}

__global__ void k_embed(const int* __restrict__ tgt, const float* __restrict__ emb,
                        float* __restrict__ X) {
    // one float4 per thread over [T*B, E]
    int i = blockIdx.x * blockDim.x + threadIdx.x;   // 0 .. T*B*E/4-1
    int row = i / (Ec/4);
    int e4  = i % (Ec/4);
    int t = row / Bc, b = row % Bc;
    int v = tgt[b*Tc + t];
    ((float4*)X)[i] = ((const float4*)(emb + (size_t)v*Ec))[e4];
}

// ---------------- big GEMM: C = A[M,K] @ W[K,N] + bias ------------------------
// MODE 0: C[m,n] = acc + bias[n]              (Z1 precompute)
// MODE 1: row remap (t*B+b) -> (b*T+t), write logits to d_out  (FC head)
// Tiles: 128x128x16, 256 threads, per-thread 8x8 via packed fp32x2.
template<int MODE>
__global__ void __launch_bounds__(256)
k_gemm(const float* __restrict__ A, const float* __restrict__ W,
       const float* __restrict__ bias, float* __restrict__ C,
       int M, int N, int K)
{
    __shared__ float sA [16][132];    // transposed A tile, padded (132*4 % 16 == 0)
    __shared__ float sBd[16][260];    // B tile with each value DUPLICATED (for fp32x2)

    const int bn  = blockIdx.x * 128;
    const int bm  = blockIdx.y * 128;
    const int tid = threadIdx.x;
    const int tx  = tid & 15, ty = tid >> 4;
    const int m0  = ty * 8,  n0 = tx * 8;

    unsigned long long acc[4][8];
    #pragma unroll
    for (int i = 0; i < 4; i++)
        #pragma unroll
        for (int j = 0; j < 8; j++) acc[i][j] = 0ull;

    for (int k0 = 0; k0 < K; k0 += 16) {
        // load A tile (128 rows x 16 cols) transposed into sA[k][m]
        #pragma unroll
        for (int r = 0; r < 2; r++) {
            int q = tid + r * 256;             // 0..511 float4s
            int row = q >> 2, c4 = (q & 3) * 4;
            float4 v = *(const float4*)(A + (size_t)(bm + row) * K + k0 + c4);
            sA[c4+0][row] = v.x; sA[c4+1][row] = v.y;
            sA[c4+2][row] = v.z; sA[c4+3][row] = v.w;
        }
        // load W tile (16 rows x 128 cols), duplicating each value
        #pragma unroll
        for (int r = 0; r < 2; r++) {
            int q = tid + r * 256;             // 0..511 float4s
            int row = q >> 5, c4 = (q & 31) * 4;
            float4 v = *(const float4*)(W + (size_t)(k0 + row) * N + bn + c4);
            *(unsigned long long*)&sBd[row][(c4+0)*2] = dup2(v.x);
            *(unsigned long long*)&sBd[row][(c4+1)*2] = dup2(v.y);
            *(unsigned long long*)&sBd[row][(c4+2)*2] = dup2(v.z);
            *(unsigned long long*)&sBd[row][(c4+3)*2] = dup2(v.w);
        }
        __syncthreads();

        #pragma unroll 4
        for (int k = 0; k < 16; k++) {
            ulonglong2 a01 = *(const ulonglong2*)&sA[k][m0];
            ulonglong2 a23 = *(const ulonglong2*)&sA[k][m0 + 4];
            unsigned long long am[4] = {a01.x, a01.y, a23.x, a23.y};
            unsigned long long wd[8];
            #pragma unroll
            for (int j = 0; j < 4; j++) {
                ulonglong2 w = *(const ulonglong2*)&sBd[k][n0*2 + j*4];
                wd[2*j] = w.x; wd[2*j+1] = w.y;
            }
            #pragma unroll
            for (int i = 0; i < 4; i++)
                #pragma unroll
                for (int j = 0; j < 8; j++)
                    ffma2(acc[i][j], am[i], wd[j]);
        }
        __syncthreads();
    }

    // epilogue
    #pragma unroll
    for (int i = 0; i < 4; i++) {
        #pragma unroll
        for (int s = 0; s < 2; s++) {
            int m = bm + m0 + 2*i + s;
            float v[8];
            #pragma unroll
            for (int j = 0; j < 8; j++) { F2U t; t.u = acc[i][j]; v[j] = s ? t.f.y : t.f.x; }
            const float* bp = bias + bn + n0;
            float4 o0 = make_float4(v[0]+bp[0], v[1]+bp[1], v[2]+bp[2], v[3]+bp[3]);
            float4 o1 = make_float4(v[4]+bp[4], v[5]+bp[5], v[6]+bp[6], v[7]+bp[7]);
            float* dst;
            if (MODE == 0) {
                dst = C + (size_t)m * N + bn + n0;
            } else {
                int t_ = m >> 6, b_ = m & 63;             // m = t*B+b
                dst = C + (size_t)(b_ * Tc + t_) * N + bn + n0;
            }
            *(float4*)dst       = o0;
            *(float4*)(dst + 4) = o1;
        }
    }
}

// ---------------- recurrence z-GEMM: z[64,4096] = init + A1@W1p + A2@W2p ------
// M=64 fixed, N tile 32 (grid 128), K=1024 per source, 128 threads,
// per-thread 4x4 via packed fp32x2 (pairs over m), BK=64.
__global__ void __launch_bounds__(128)
k_zgemm(const float* __restrict__ zinit, const float* __restrict__ bias,
        const float* __restrict__ A1, const float* __restrict__ W1p,
        const float* __restrict__ A2, const float* __restrict__ W2p,
        float* __restrict__ zout)
{
    __shared__ float sA [64][68];     // transposed A tile [k][m]
    __shared__ float sBd[64][68];     // W tile duplicated [k][2n]

    const int bn  = blockIdx.x * 32;
    const int tid = threadIdx.x;
    const int tx  = tid & 7, ty = tid >> 3;
    const int m0  = ty * 4, n0 = tx * 4;

    unsigned long long acc[2][4];
    #pragma unroll
    for (int i = 0; i < 2; i++)
        #pragma unroll
        for (int j = 0; j < 4; j++) acc[i][j] = 0ull;

    #pragma unroll 1
    for (int src = 0; src < 2; src++) {
        const float* A = src ? A2 : A1;
        const float* W = src ? W2p : W1p;
        if (A == nullptr) continue;
        for (int k0 = 0; k0 < Hc; k0 += 64) {
            // A tile: 64 rows x 64 cols -> 1024 float4, 8 per thread
            #pragma unroll
            for (int r = 0; r < 8; r++) {
                int q = tid + r * 128;
                int row = q >> 4, c4 = (q & 15) * 4;
                float4 v = *(const float4*)(A + (size_t)row * Hc + k0 + c4);
                sA[c4+0][row] = v.x; sA[c4+1][row] = v.y;
                sA[c4+2][row] = v.z; sA[c4+3][row] = v.w;
            }
            // W tile: 64 rows x 32 cols -> 512 float4, 4 per thread, duplicated
            #pragma unroll
            for (int r = 0; r < 4; r++) {
                int q = tid + r * 128;
                int row = q >> 3, c4 = (q & 7) * 4;
                float4 v = *(const float4*)(W + (size_t)(k0 + row) * Gc + bn + c4);
                *(unsigned long long*)&sBd[row][(c4+0)*2] = dup2(v.x);
                *(unsigned long long*)&sBd[row][(c4+1)*2] = dup2(v.y);
                *(unsigned long long*)&sBd[row][(c4+2)*2] = dup2(v.z);
                *(unsigned long long*)&sBd[row][(c4+3)*2] = dup2(v.w);
            }
            __syncthreads();

            #pragma unroll 16
            for (int k = 0; k < 64; k++) {
                ulonglong2 a  = *(const ulonglong2*)&sA[k][m0];
                unsigned long long am[2] = {a.x, a.y};
                ulonglong2 w0 = *(const ulonglong2*)&sBd[k][n0*2];
                ulonglong2 w1 = *(const ulonglong2*)&sBd[k][n0*2 + 4];
                unsigned long long wd[4] = {w0.x, w0.y, w1.x, w1.y};
                #pragma unroll
                for (int i = 0; i < 2; i++)
                    #pragma unroll
                    for (int j = 0; j < 4; j++)
                        ffma2(acc[i][j], am[i], wd[j]);
            }
            __syncthreads();
        }
    }

    // epilogue: add zinit (precomputed x@W1+b1) or bias
    #pragma unroll
    for (int i = 0; i < 2; i++) {
        #pragma unroll
        for (int s = 0; s < 2; s++) {
            int m = m0 + 2*i + s;
            float v[4];
            #pragma unroll
            for (int j = 0; j < 4; j++) { F2U t; t.u = acc[i][j]; v[j] = s ? t.f.y : t.f.x; }
            float4 o;
            if (zinit) {
                float4 zi = *(const float4*)(zinit + (size_t)m * Gc + bn + n0);
                o = make_float4(v[0]+zi.x, v[1]+zi.y, v[2]+zi.z, v[3]+zi.w);
            } else {
                float4 bb = *(const float4*)(bias + bn + n0);
                o = make_float4(v[0]+bb.x, v[1]+bb.y, v[2]+bb.z, v[3]+bb.w);
            }
            *(float4*)(zout + (size_t)m * Gc + bn + n0) = o;
        }
    }
}

// ---------------- LSTM gates --------------------------------------------------
__device__ __forceinline__ float sigm(float x) { return 1.f / (1.f + __expf(-x)); }

__global__ void k_gate(const float* __restrict__ z, float* __restrict__ h,
                       float* __restrict__ c, float* __restrict__ h4row)
{
    int i = blockIdx.x * blockDim.x + threadIdx.x;  // 0 .. B*H-1
    int b = i >> 10, u = i & 1023;
    const float* zr = z + (size_t)b * Gc + u;
    float zi = zr[0], zf = zr[1024], zg = zr[2048], zo = zr[3072];
    float cn = sigm(zf) * c[i] + sigm(zi) * tanhf(zg);
    float hn = sigm(zo) * tanhf(cn);
    c[i] = cn;
    h[i] = hn;
    if (h4row) h4row[i] = hn;
}

// ---------------- row softmax over V=32000, in place in d_out ----------------
__global__ void __launch_bounds__(256) k_softmax(float* __restrict__ out)
{
    const int row = blockIdx.x;
    float* p = out + (size_t)row * Vc;
    const int tid = threadIdx.x;
    __shared__ float red[8];

    float mx = -3.4e38f;
    for (int i = tid; i < Vc; i += 256) mx = fmaxf(mx, p[i]);
    #pragma unroll
    for (int o = 16; o > 0; o >>= 1) mx = fmaxf(mx, __shfl_xor_sync(0xffffffffu, mx, o));
    if ((tid & 31) == 0) red[tid >> 5] = mx;
    __syncthreads();
    mx = red[0];
    #pragma unroll
    for (int j = 1; j < 8; j++) mx = fmaxf(mx, red[j]);

    float sum = 0.f;
    for (int i = tid; i < Vc; i += 256) { float e = __expf(p[i] - mx); p[i] = e; sum += e; }
    #pragma unroll
    for (int o = 16; o > 0; o >>= 1) sum += __shfl_xor_sync(0xffffffffu, sum, o);
    __syncthreads();
    if ((tid & 31) == 0) red[tid >> 5] = sum;
    __syncthreads();
    sum = red[0];
    #pragma unroll
    for (int j = 1; j < 8; j++) sum += red[j];

    float inv = 1.f / sum;
    for (int i = tid; i < Vc; i += 256) p[i] *= inv;
}

// ---------------- launch ------------------------------------------------------
extern "C" void kernel_launch(void* const* d_in, const int* in_sizes, int n_in,
                              void* d_out, int out_size)
{
    const int*   tgt = (const int*)  d_in[0];
    const float* h1  = (const float*)d_in[1],  *c1 = (const float*)d_in[2];
    const float* h2  = (const float*)d_in[3],  *c2 = (const float*)d_in[4];
    const float* h3  = (const float*)d_in[5],  *c3 = (const float*)d_in[6];
    const float* h4  = (const float*)d_in[7],  *c4 = (const float*)d_in[8];
    const float* emb = (const float*)d_in[9];
    const float* W1  = (const float*)d_in[10], *U1 = (const float*)d_in[11], *b1 = (const float*)d_in[12];
    const float* W2  = (const float*)d_in[13], *U2 = (const float*)d_in[14], *b2 = (const float*)d_in[15];
    const float* W3  = (const float*)d_in[16], *U3 = (const float*)d_in[17], *b3 = (const float*)d_in[18];
    const float* W4  = (const float*)d_in[19], *U4 = (const float*)d_in[20], *b4 = (const float*)d_in[21];
    const float* Wfc = (const float*)d_in[22], *bfc = (const float*)d_in[23];
    float* out = (float*)d_out;

    float *pX, *pZ1, *pZt, *phb, *pcb, *pH4;
    cudaGetSymbolAddress((void**)&pX,  g_X);
    cudaGetSymbolAddress((void**)&pZ1, g_Z1);
    cudaGetSymbolAddress((void**)&pZt, g_Zt);
    cudaGetSymbolAddress((void**)&phb, g_h);
    cudaGetSymbolAddress((void**)&pcb, g_c);
    cudaGetSymbolAddress((void**)&pH4, g_H4);
    float* ph[4]; float* pc[4];
    for (int l = 0; l < 4; l++) { ph[l] = phb + (size_t)l * Bc * Hc; pc[l] = pcb + (size_t)l * Bc * Hc; }

    // state init + embedding gather
    k_init <<<Bc*Hc/256, 256>>>(h1, c1, h2, c2, h3, c3, h4, c4, phb, pcb);
    k_embed<<<Tc*Bc*Ec/4/256, 256>>>(tgt, emb, pX);

    // hoisted: Z1 = X @ W1 + b1 for all timesteps  [4096 x 4096, K=512]
    k_gemm<0><<<dim3(Gc/128, (Tc*Bc)/128), 256>>>(pX, W1, b1, pZ1, Tc*Bc, Gc, Ec);

    const float* Wl[4] = {nullptr, W2, W3, W4};
    const float* Ul[4] = {U1, U2, U3, U4};
    const float* bl[4] = {nullptr, b2, b3, b4};

    for (int t = 0; t < Tc; t++) {
        // layer 1: z = Z1[t] + h1 @ U1
        k_zgemm<<<128, 128>>>(pZ1 + (size_t)t * Bc * Gc, nullptr,
                              nullptr, nullptr, ph[0], Ul[0], pZt);
        k_gate<<<Bc*Hc/256, 256>>>(pZt, ph[0], pc[0], nullptr);
        // layers 2..4: z = b + h_{l-1} @ W + h_l @ U
        for (int l = 1; l < 4; l++) {
            k_zgemm<<<128, 128>>>(nullptr, bl[l],
                                  ph[l-1], Wl[l], ph[l], Ul[l], pZt);
            k_gate<<<Bc*Hc/256, 256>>>(pZt, ph[l], pc[l],
                                       (l == 3) ? (pH4 + (size_t)t * Bc * Hc) : nullptr);
        }
    }

    // hoisted FC head: logits (row-remapped to [B,T,V]) then softmax in place
    k_gemm<1><<<dim3(Vc/128, (Tc*Bc)/128), 256>>>(pH4, Wfc, bfc, out, Tc*Bc, Vc, Hc);
    k_softmax<<<Tc*Bc, 256>>>(out);
}

// round 8
// speedup vs baseline: 1.8593x; 1.8515x over previous
#include <cuda_runtime.h>
#include <math.h>

#define Bc 64
#define Tc 64
#define Hc 1024
#define Vc 32000
#define Ec 512
#define Gc 4096

__device__ float g_X [Tc*Bc*Ec];
__device__ float g_Z1[(size_t)Tc*Bc*Gc];
__device__ float g_h [4][2][Bc*Hc];     // ping-pong h per layer
__device__ float g_c [4][Bc*Hc];
__device__ float g_H4[Tc*Bc*Hc];

__device__ __forceinline__ unsigned rna_u(float v){unsigned r;asm("cvt.rna.tf32.f32 %0,%1;":"=r"(r):"f"(v));return r;}
__device__ __forceinline__ float rna_f(float v){return __uint_as_float(rna_u(v));}
__device__ __forceinline__ float sigm(float x){return 1.f/(1.f+__expf(-x));}

__device__ __forceinline__ void mma8(float* d, const unsigned* a, const unsigned* b){
    asm volatile("mma.sync.aligned.m16n8k8.row.col.f32.tf32.tf32.f32 "
        "{%0,%1,%2,%3},{%4,%5,%6,%7},{%8,%9},{%0,%1,%2,%3};"
        :"+f"(d[0]),"+f"(d[1]),"+f"(d[2]),"+f"(d[3])
        :"r"(a[0]),"r"(a[1]),"r"(a[2]),"r"(a[3]),"r"(b[0]),"r"(b[1]));
}

// ---------------- init / embed ----------------
__global__ void k_init(const float* __restrict__ h1,const float* __restrict__ c1,
                       const float* __restrict__ h2,const float* __restrict__ c2,
                       const float* __restrict__ h3,const float* __restrict__ c3,
                       const float* __restrict__ h4,const float* __restrict__ c4,
                       float* __restrict__ ph, float* __restrict__ pc){
    int i = blockIdx.x*blockDim.x + threadIdx.x;  const int S = Bc*Hc;
    ph[(0*2)*S+i]=h1[i]; pc[0*S+i]=c1[i];
    ph[(1*2)*S+i]=h2[i]; pc[1*S+i]=c2[i];
    ph[(2*2)*S+i]=h3[i]; pc[2*S+i]=c3[i];
    ph[(3*2)*S+i]=h4[i]; pc[3*S+i]=c4[i];
}

__global__ void k_embed(const int* __restrict__ tgt, const float* __restrict__ emb,
                        float* __restrict__ X){
    int i = blockIdx.x*blockDim.x + threadIdx.x;   // T*B*E/4 threads
    int row = i/(Ec/4), e4 = i%(Ec/4);
    int t = row/Bc, b = row%Bc;
    int v = tgt[b*Tc + t];
    ((float4*)X)[i] = ((const float4*)(emb + (size_t)v*Ec))[e4];
}

// ---------------- big tf32 GEMM: C = A[M,K]@W[K,N] + bias --------------------
// MODE 0: direct rows (Z1). MODE 1: row remap (t*B+b)->(b*T+t) (FC logits).
// 128x128 tile, BK=32, 256 thr = 8 warps (2m x 4n), warp tile 64x32.
#define GP 20   // float2 pitch
template<int MODE>
__global__ void __launch_bounds__(256)
k_gemm(const float* __restrict__ A, const float* __restrict__ W,
       const float* __restrict__ bias, float* __restrict__ C, int N, int K)
{
    __shared__ float2 sA[128*GP];   // [m][pair(k,k+4)] rna-rounded
    __shared__ float2 sB[128*GP];   // [n][pair(k,k+4)]

    const int bn = blockIdx.x*128, bm = blockIdx.y*128;
    const int tid = threadIdx.x, lane = tid&31, wid = tid>>5;
    const int wM = wid>>2, wN = wid&3, grp = lane>>2, tg = lane&3;

    float acc[4][4][4];
    #pragma unroll
    for(int a=0;a<4;a++)for(int b=0;b<4;b++)for(int c=0;c<4;c++)acc[a][b][c]=0.f;

    for (int k0 = 0; k0 < K; k0 += 32) {
        #pragma unroll
        for (int i=0;i<4;i++){
            int q = tid + i*256;          // A: 128x32
            int m = q>>3, c4 = q&7;
            float4 v = *(const float4*)(A + (size_t)(bm+m)*K + k0 + c4*4);
            float2* d = &sA[m*GP + (c4>>1)*4];
            float vv[4]={v.x,v.y,v.z,v.w};
            if (c4&1){ d[0].y=rna_f(vv[0]); d[1].y=rna_f(vv[1]); d[2].y=rna_f(vv[2]); d[3].y=rna_f(vv[3]); }
            else     { d[0].x=rna_f(vv[0]); d[1].x=rna_f(vv[1]); d[2].x=rna_f(vv[2]); d[3].x=rna_f(vv[3]); }
        }
        #pragma unroll
        for (int i=0;i<4;i++){
            int q = tid + i*256;          // B: 32x128
            int k = q>>5, n4 = q&31;
            float4 v = *(const float4*)(W + (size_t)(k0+k)*N + bn + n4*4);
            int slot = (k>>3)*4 + (k&3);  int up = (k>>2)&1;
            float vv[4]={v.x,v.y,v.z,v.w};
            #pragma unroll
            for (int j=0;j<4;j++){
                if (up) sB[(n4*4+j)*GP + slot].y = rna_f(vv[j]);
                else    sB[(n4*4+j)*GP + slot].x = rna_f(vv[j]);
            }
        }
        __syncthreads();

        #pragma unroll
        for (int k8=0;k8<4;k8++){
            unsigned af[4][4], bf[4][2];
            #pragma unroll
            for (int mi=0;mi<4;mi++){
                int r = wM*64 + mi*16 + grp;
                float2 p0 = sA[r*GP + k8*4 + tg];
                float2 p1 = sA[(r+8)*GP + k8*4 + tg];
                af[mi][0]=__float_as_uint(p0.x); af[mi][1]=__float_as_uint(p1.x);
                af[mi][2]=__float_as_uint(p0.y); af[mi][3]=__float_as_uint(p1.y);
            }
            #pragma unroll
            for (int ni=0;ni<4;ni++){
                float2 q2 = sB[(wN*32 + ni*8 + grp)*GP + k8*4 + tg];
                bf[ni][0]=__float_as_uint(q2.x); bf[ni][1]=__float_as_uint(q2.y);
            }
            #pragma unroll
            for (int mi=0;mi<4;mi++)
                #pragma unroll
                for (int ni=0;ni<4;ni++)
                    mma8(acc[mi][ni], af[mi], bf[ni]);
        }
        __syncthreads();
    }

    #pragma unroll
    for (int mi=0;mi<4;mi++){
        #pragma unroll
        for (int r=0;r<2;r++){
            int m = bm + wM*64 + mi*16 + grp + 8*r;
            size_t rowOut = MODE ? ((size_t)(m&63)*Tc + (m>>6)) : (size_t)m;
            #pragma unroll
            for (int ni=0;ni<4;ni++){
                int col = bn + wN*32 + ni*8 + 2*tg;
                float2 o = make_float2(acc[mi][ni][2*r]   + bias[col],
                                       acc[mi][ni][2*r+1] + bias[col+1]);
                *(float2*)(C + rowOut*N + col) = o;
            }
        }
    }
}

// ---------------- fused LSTM cell (3xTF32) -----------------------------------
// z[64 x 32cols] = (zinit|bias) + A1@W + A2@U for units u0..u0+7, gates fused.
// Grid 128, 256 thr = 8 warps (2m x 4n), warp tile 32x8, BK=128.
#define APITCH 68
#define CELL_SMEM (96*APITCH*16)   // 104448 B
__global__ void __launch_bounds__(256)
k_cell(const float* __restrict__ A1, const float* __restrict__ W1p,
       const float* __restrict__ A2, const float* __restrict__ W2p,
       const float* __restrict__ zinit, const float* __restrict__ bias,
       float* __restrict__ cst, float* __restrict__ hout, float* __restrict__ h4row)
{
    extern __shared__ float4 smem4[];
    float4* sA = smem4;               // [64][APITCH]  (hi,lo,hi+4,lo+4)
    float4* sB = smem4 + 64*APITCH;   // [32][APITCH]
    float*  sE = (float*)smem4;       // epilogue alias [64][33]

    const int u0 = blockIdx.x*8;
    const int tid = threadIdx.x, lane = tid&31, wid = tid>>5;
    const int wM = wid>>2, wN = wid&3, grp = lane>>2, tg = lane&3;

    float acc[2][4];
    #pragma unroll
    for(int i=0;i<2;i++)for(int q=0;q<4;q++)acc[i][q]=0.f;

    #pragma unroll 1
    for (int s=0;s<2;s++){
        const float* A = s?A2:A1; const float* W = s?W2p:W1p;
        if (!A) continue;
        #pragma unroll 1
        for (int kt=0;kt<8;kt++){
            int k0 = kt*128;
            #pragma unroll
            for (int i=0;i<8;i++){        // A 64x128, split hi/lo
                int q = tid + i*256; int m = q>>5, c4 = q&31;
                float4 v = *(const float4*)(A + (size_t)m*Hc + k0 + c4*4);
                float* d = (float*)(sA + m*APITCH + (c4>>1)*4) + (c4&1)*2;
                float vv[4]={v.x,v.y,v.z,v.w};
                #pragma unroll
                for (int j=0;j<4;j++){ float h=rna_f(vv[j]); d[j*4]=h; d[j*4+1]=rna_f(vv[j]-h); }
            }
            #pragma unroll
            for (int i=0;i<4;i++){        // B 128x32 gathered, split hi/lo
                int q = tid + i*256; int k = q>>3, ng = q&7;
                int gcol = (ng>>1)*1024 + u0 + (ng&1)*4;
                float4 v = *(const float4*)(W + (size_t)(k0+k)*Gc + gcol);
                int slot = (k>>3)*4 + (k&3); int up = (k>>2)&1;
                float vv[4]={v.x,v.y,v.z,v.w};
                #pragma unroll
                for (int j=0;j<4;j++){
                    float* d = (float*)(sB + (ng*4+j)*APITCH + slot) + up*2;
                    float h=rna_f(vv[j]); d[0]=h; d[1]=rna_f(vv[j]-h);
                }
            }
            __syncthreads();
            #pragma unroll
            for (int k8=0;k8<16;k8++){
                unsigned ah[2][4], al[2][4], bh[2], bl[2];
                #pragma unroll
                for (int mi=0;mi<2;mi++){
                    int r = wM*32 + mi*16 + grp;
                    float4 p0 = sA[r*APITCH + k8*4 + tg];
                    float4 p1 = sA[(r+8)*APITCH + k8*4 + tg];
                    ah[mi][0]=__float_as_uint(p0.x); ah[mi][1]=__float_as_uint(p1.x);
                    ah[mi][2]=__float_as_uint(p0.z); ah[mi][3]=__float_as_uint(p1.z);
                    al[mi][0]=__float_as_uint(p0.y); al[mi][1]=__float_as_uint(p1.y);
                    al[mi][2]=__float_as_uint(p0.w); al[mi][3]=__float_as_uint(p1.w);
                }
                float4 q4 = sB[(wN*8+grp)*APITCH + k8*4 + tg];
                bh[0]=__float_as_uint(q4.x); bh[1]=__float_as_uint(q4.z);
                bl[0]=__float_as_uint(q4.y); bl[1]=__float_as_uint(q4.w);
                #pragma unroll
                for (int mi=0;mi<2;mi++){
                    mma8(acc[mi], ah[mi], bh);
                    mma8(acc[mi], ah[mi], bl);
                    mma8(acc[mi], al[mi], bh);
                }
            }
            __syncthreads();
        }
    }

    // z tile -> smem, then fused gates
    #pragma unroll
    for (int mi=0;mi<2;mi++){
        #pragma unroll
        for (int r=0;r<2;r++){
            int m = wM*32 + mi*16 + grp + 8*r, col = wN*8 + 2*tg;
            sE[m*33+col]   = acc[mi][2*r];
            sE[m*33+col+1] = acc[mi][2*r+1];
        }
    }
    __syncthreads();
    #pragma unroll
    for (int i=0;i<2;i++){
        int q = tid + i*256; int j = q&7, m = q>>3;
        int gidx = m*Hc + u0 + j;
        float zi,zf,zg_,zo;
        if (zinit){
            const float* zr = zinit + (size_t)m*Gc + u0 + j;
            zi  = sE[m*33+j]    + zr[0];
            zf  = sE[m*33+8+j]  + zr[1024];
            zg_ = sE[m*33+16+j] + zr[2048];
            zo  = sE[m*33+24+j] + zr[3072];
        } else {
            const float* br = bias + u0 + j;
            zi  = sE[m*33+j]    + br[0];
            zf  = sE[m*33+8+j]  + br[1024];
            zg_ = sE[m*33+16+j] + br[2048];
            zo  = sE[m*33+24+j] + br[3072];
        }
        float cn = sigm(zf)*cst[gidx] + sigm(zi)*tanhf(zg_);
        float hn = sigm(zo)*tanhf(cn);
        cst[gidx]=cn; hout[gidx]=hn;
        if (h4row) h4row[gidx]=hn;
    }
}

// ---------------- row softmax over V=32000, in place -------------------------
__global__ void __launch_bounds__(256) k_softmax(float* __restrict__ out)
{
    const int row = blockIdx.x;
    float* p = out + (size_t)row*Vc;
    const int tid = threadIdx.x;
    __shared__ float red[8];

    float mx = -3.4e38f;
    for (int i=tid;i<Vc;i+=256) mx = fmaxf(mx, p[i]);
    #pragma unroll
    for (int o=16;o>0;o>>=1) mx = fmaxf(mx, __shfl_xor_sync(0xffffffffu,mx,o));
    if ((tid&31)==0) red[tid>>5]=mx;
    __syncthreads();
    mx = red[0];
    #pragma unroll
    for (int j=1;j<8;j++) mx = fmaxf(mx, red[j]);

    float sum = 0.f;
    for (int i=tid;i<Vc;i+=256){ float e=__expf(p[i]-mx); p[i]=e; sum+=e; }
    #pragma unroll
    for (int o=16;o>0;o>>=1) sum += __shfl_xor_sync(0xffffffffu,sum,o);
    __syncthreads();
    if ((tid&31)==0) red[tid>>5]=sum;
    __syncthreads();
    sum = red[0];
    #pragma unroll
    for (int j=1;j<8;j++) sum += red[j];
    float inv = 1.f/sum;
    for (int i=tid;i<Vc;i+=256) p[i]*=inv;
}

// ---------------- launch -----------------------------------------------------
extern "C" void kernel_launch(void* const* d_in, const int* in_sizes, int n_in,
                              void* d_out, int out_size)
{
    const int*   tgt = (const int*)  d_in[0];
    const float* h1  = (const float*)d_in[1],  *c1 = (const float*)d_in[2];
    const float* h2  = (const float*)d_in[3],  *c2 = (const float*)d_in[4];
    const float* h3  = (const float*)d_in[5],  *c3 = (const float*)d_in[6];
    const float* h4  = (const float*)d_in[7],  *c4 = (const float*)d_in[8];
    const float* emb = (const float*)d_in[9];
    const float* W1  = (const float*)d_in[10], *U1 = (const float*)d_in[11], *b1 = (const float*)d_in[12];
    const float* W2  = (const float*)d_in[13], *U2 = (const float*)d_in[14], *b2 = (const float*)d_in[15];
    const float* W3  = (const float*)d_in[16], *U3 = (const float*)d_in[17], *b3 = (const float*)d_in[18];
    const float* W4  = (const float*)d_in[19], *U4 = (const float*)d_in[20], *b4 = (const float*)d_in[21];
    const float* Wfc = (const float*)d_in[22], *bfc = (const float*)d_in[23];
    float* out = (float*)d_out;

    float *pX,*pZ1,*phb,*pcb,*pH4;
    cudaGetSymbolAddress((void**)&pX,  g_X);
    cudaGetSymbolAddress((void**)&pZ1, g_Z1);
    cudaGetSymbolAddress((void**)&phb, g_h);
    cudaGetSymbolAddress((void**)&pcb, g_c);
    cudaGetSymbolAddress((void**)&pH4, g_H4);
    cudaFuncSetAttribute(k_cell, cudaFuncAttributeMaxDynamicSharedMemorySize, CELL_SMEM);

    const int S = Bc*Hc;
    k_init <<<S/256, 256>>>(h1,c1,h2,c2,h3,c3,h4,c4, phb, pcb);
    k_embed<<<Tc*Bc*Ec/4/256, 256>>>(tgt, emb, pX);
    k_gemm<0><<<dim3(Gc/128,(Tc*Bc)/128), 256>>>(pX, W1, b1, pZ1, Gc, Ec);

    const float* Wl[4] = {nullptr, W2, W3, W4};
    const float* Ul[4] = {U1, U2, U3, U4};
    const float* bl[4] = {nullptr, b2, b3, b4};

    for (int t = 0; t < Tc; t++) {
        int pr = t & 1, pw = 1 - pr;
        // layer 1: z = Z1[t] + h1@U1
        k_cell<<<128,256,CELL_SMEM>>>(nullptr, nullptr,
                                      phb + (0*2+pr)*S, Ul[0],
                                      pZ1 + (size_t)t*Bc*Gc, nullptr,
                                      pcb + 0*S, phb + (0*2+pw)*S, nullptr);
        for (int l = 1; l < 4; l++) {
            k_cell<<<128,256,CELL_SMEM>>>(phb + ((l-1)*2+pw)*S, Wl[l],
                                          phb + (l*2+pr)*S,     Ul[l],
                                          nullptr, bl[l],
                                          pcb + l*S, phb + (l*2+pw)*S,
                                          (l==3) ? (pH4 + (size_t)t*S) : nullptr);
        }
    }

    k_gemm<1><<<dim3(Vc/128,(Tc*Bc)/128), 256>>>(pH4, Wfc, bfc, out, Vc, Hc);
    k_softmax<<<Tc*Bc, 256>>>(out);
}

// round 11
// speedup vs baseline: 1.8685x; 1.0050x over previous
#include <cuda_runtime.h>
#include <math.h>

#define Bc 64
#define Tc 64
#define Hc 1024
#define Vc 32000
#define Ec 512
#define Gc 4096

__device__ float g_X [Tc*Bc*Ec];
__device__ float g_Z1[(size_t)Tc*Bc*Gc];
__device__ float g_h [4][2][Bc*Hc];     // ping-pong h per layer
__device__ float g_c [4][Bc*Hc];
__device__ float g_H4[Tc*Bc*Hc];

__device__ __forceinline__ unsigned rna_u(float v){unsigned r;asm("cvt.rna.tf32.f32 %0,%1;":"=r"(r):"f"(v));return r;}
__device__ __forceinline__ float rna_f(float v){return __uint_as_float(rna_u(v));}
__device__ __forceinline__ float sigm(float x){return 1.f/(1.f+__expf(-x));}

__device__ __forceinline__ void mma8(float* d, const unsigned* a, const unsigned* b){
    asm volatile("mma.sync.aligned.m16n8k8.row.col.f32.tf32.tf32.f32 "
        "{%0,%1,%2,%3},{%4,%5,%6,%7},{%8,%9},{%0,%1,%2,%3};"
        :"+f"(d[0]),"+f"(d[1]),"+f"(d[2]),"+f"(d[3])
        :"r"(a[0]),"r"(a[1]),"r"(a[2]),"r"(a[3]),"r"(b[0]),"r"(b[1]));
}

// ---------------- init / embed ----------------
__global__ void k_init(const float* __restrict__ h1,const float* __restrict__ c1,
                       const float* __restrict__ h2,const float* __restrict__ c2,
                       const float* __restrict__ h3,const float* __restrict__ c3,
                       const float* __restrict__ h4,const float* __restrict__ c4,
                       float* __restrict__ ph, float* __restrict__ pc){
    int i = blockIdx.x*blockDim.x + threadIdx.x;  const int S = Bc*Hc;
    ph[(0*2)*S+i]=h1[i]; pc[0*S+i]=c1[i];
    ph[(1*2)*S+i]=h2[i]; pc[1*S+i]=c2[i];
    ph[(2*2)*S+i]=h3[i]; pc[2*S+i]=c3[i];
    ph[(3*2)*S+i]=h4[i]; pc[3*S+i]=c4[i];
}

__global__ void k_embed(const int* __restrict__ tgt, const float* __restrict__ emb,
                        float* __restrict__ X){
    int i = blockIdx.x*blockDim.x + threadIdx.x;
    int row = i/(Ec/4), e4 = i%(Ec/4);
    int t = row/Bc, b = row%Bc;
    int v = tgt[b*Tc + t];
    ((float4*)X)[i] = ((const float4*)(emb + (size_t)v*Ec))[e4];
}

// ---------------- big tf32 GEMM: C = A[M,K]@W[K,N] + bias --------------------
// bm on blockIdx.x (FAST dim) so resident blocks share W column tiles -> W
// streams once. Register-prefetch double buffering over K tiles.
#define GP 20
template<int MODE>
__global__ void __launch_bounds__(256)
k_gemm(const float* __restrict__ A, const float* __restrict__ W,
       const float* __restrict__ bias, float* __restrict__ C, int N, int K)
{
    __shared__ float2 sA[128*GP];
    __shared__ float2 sB[128*GP];

    const int bm = blockIdx.x*128, bn = blockIdx.y*128;   // bm FAST
    const int tid = threadIdx.x, lane = tid&31, wid = tid>>5;
    const int wM = wid>>2, wN = wid&3, grp = lane>>2, tg = lane&3;

    float acc[4][4][4];
    #pragma unroll
    for(int a=0;a<4;a++)for(int b=0;b<4;b++)for(int c=0;c<4;c++)acc[a][b][c]=0.f;

    float4 pa[4], pb[4];
    // prefetch tile 0
    #pragma unroll
    for (int i=0;i<4;i++){
        int q = tid + i*256; int m = q>>3, c4 = q&7;
        pa[i] = *(const float4*)(A + (size_t)(bm+m)*K + c4*4);
    }
    #pragma unroll
    for (int i=0;i<4;i++){
        int q = tid + i*256; int k = q>>5, n4 = q&31;
        pb[i] = *(const float4*)(W + (size_t)k*N + bn + n4*4);
    }

    for (int k0 = 0; k0 < K; k0 += 32) {
        // store prefetched tile to smem (rna-rounded, (k,k+4) pair packing)
        #pragma unroll
        for (int i=0;i<4;i++){
            int q = tid + i*256; int m = q>>3, c4 = q&7;
            float2* d = &sA[m*GP + (c4>>1)*4];
            float vv[4]={pa[i].x,pa[i].y,pa[i].z,pa[i].w};
            if (c4&1){ d[0].y=rna_f(vv[0]); d[1].y=rna_f(vv[1]); d[2].y=rna_f(vv[2]); d[3].y=rna_f(vv[3]); }
            else     { d[0].x=rna_f(vv[0]); d[1].x=rna_f(vv[1]); d[2].x=rna_f(vv[2]); d[3].x=rna_f(vv[3]); }
        }
        #pragma unroll
        for (int i=0;i<4;i++){
            int q = tid + i*256; int k = q>>5, n4 = q&31;
            int slot = (k>>3)*4 + (k&3);  int up = (k>>2)&1;
            float vv[4]={pb[i].x,pb[i].y,pb[i].z,pb[i].w};
            #pragma unroll
            for (int j=0;j<4;j++){
                if (up) sB[(n4*4+j)*GP + slot].y = rna_f(vv[j]);
                else    sB[(n4*4+j)*GP + slot].x = rna_f(vv[j]);
            }
        }
        __syncthreads();

        // prefetch next tile while MMAing this one
        if (k0 + 32 < K){
            #pragma unroll
            for (int i=0;i<4;i++){
                int q = tid + i*256; int m = q>>3, c4 = q&7;
                pa[i] = *(const float4*)(A + (size_t)(bm+m)*K + (k0+32) + c4*4);
            }
            #pragma unroll
            for (int i=0;i<4;i++){
                int q = tid + i*256; int k = q>>5, n4 = q&31;
                pb[i] = *(const float4*)(W + (size_t)(k0+32+k)*N + bn + n4*4);
            }
        }

        #pragma unroll
        for (int k8=0;k8<4;k8++){
            unsigned af[4][4], bf[4][2];
            #pragma unroll
            for (int mi=0;mi<4;mi++){
                int r = wM*64 + mi*16 + grp;
                float2 p0 = sA[r*GP + k8*4 + tg];
                float2 p1 = sA[(r+8)*GP + k8*4 + tg];
                af[mi][0]=__float_as_uint(p0.x); af[mi][1]=__float_as_uint(p1.x);
                af[mi][2]=__float_as_uint(p0.y); af[mi][3]=__float_as_uint(p1.y);
            }
            #pragma unroll
            for (int ni=0;ni<4;ni++){
                float2 q2 = sB[(wN*32 + ni*8 + grp)*GP + k8*4 + tg];
                bf[ni][0]=__float_as_uint(q2.x); bf[ni][1]=__float_as_uint(q2.y);
            }
            #pragma unroll
            for (int mi=0;mi<4;mi++)
                #pragma unroll
                for (int ni=0;ni<4;ni++)
                    mma8(acc[mi][ni], af[mi], bf[ni]);
        }
        __syncthreads();
    }

    #pragma unroll
    for (int mi=0;mi<4;mi++){
        #pragma unroll
        for (int r=0;r<2;r++){
            int m = bm + wM*64 + mi*16 + grp + 8*r;
            size_t rowOut = MODE ? ((size_t)(m&63)*Tc + (m>>6)) : (size_t)m;
            #pragma unroll
            for (int ni=0;ni<4;ni++){
                int col = bn + wN*32 + ni*8 + 2*tg;
                float2 o = make_float2(acc[mi][ni][2*r]   + bias[col],
                                       acc[mi][ni][2*r+1] + bias[col+1]);
                *(float2*)(C + rowOut*N + col) = o;
            }
        }
    }
}

// ---------------- fused LSTM cell (3xTF32, reg-prefetch pipelined) -----------
#define APITCH 68
#define CELL_SMEM (96*APITCH*16)   // 104448 B
__global__ void __launch_bounds__(256)
k_cell(const float* __restrict__ A1, const float* __restrict__ W1p,
       const float* __restrict__ A2, const float* __restrict__ W2p,
       const float* __restrict__ zinit, const float* __restrict__ bias,
       float* __restrict__ cst, float* __restrict__ hout, float* __restrict__ h4row)
{
    extern __shared__ float4 smem4[];
    float4* sA = smem4;               // [64][APITCH]
    float4* sB = smem4 + 64*APITCH;   // [32][APITCH]
    float*  sE = (float*)smem4;       // epilogue alias [64][33]

    const int u0 = blockIdx.x*8;
    const int tid = threadIdx.x, lane = tid&31, wid = tid>>5;
    const int wM = wid>>2, wN = wid&3, grp = lane>>2, tg = lane&3;

    float acc[2][4];
    #pragma unroll
    for(int i=0;i<2;i++)for(int q=0;q<4;q++)acc[i][q]=0.f;

    const float* As[2] = {A1, A2};
    const float* Ws[2] = {W1p, W2p};
    const int t0 = A1 ? 0 : 8;

    float4 va[8], vb[4];
    // prefetch tile t0
    {
        const float* A = As[t0>>3]; const float* W = Ws[t0>>3]; int k0 = (t0&7)*128;
        #pragma unroll
        for (int i=0;i<8;i++){
            int q = tid + i*256; int m = q>>5, c4 = q&31;
            va[i] = *(const float4*)(A + (size_t)m*Hc + k0 + c4*4);
        }
        #pragma unroll
        for (int i=0;i<4;i++){
            int q = tid + i*256; int k = q>>3, ng = q&7;
            int gcol = (ng>>1)*1024 + u0 + (ng&1)*4;
            vb[i] = *(const float4*)(W + (size_t)(k0+k)*Gc + gcol);
        }
    }

    for (int tt = t0; tt < 16; tt++){
        // store prefetched tile to smem with hi/lo split
        #pragma unroll
        for (int i=0;i<8;i++){
            int q = tid + i*256; int m = q>>5, c4 = q&31;
            float* d = (float*)(sA + m*APITCH + (c4>>1)*4) + (c4&1)*2;
            float vv[4]={va[i].x,va[i].y,va[i].z,va[i].w};
            #pragma unroll
            for (int j=0;j<4;j++){ float h=rna_f(vv[j]); d[j*4]=h; d[j*4+1]=rna_f(vv[j]-h); }
        }
        #pragma unroll
        for (int i=0;i<4;i++){
            int q = tid + i*256; int k = q>>3, ng = q&7;
            int slot = (k>>3)*4 + (k&3); int up = (k>>2)&1;
            float vv[4]={vb[i].x,vb[i].y,vb[i].z,vb[i].w};
            #pragma unroll
            for (int j=0;j<4;j++){
                float* d = (float*)(sB + (ng*4+j)*APITCH + slot) + up*2;
                float h=rna_f(vv[j]); d[0]=h; d[1]=rna_f(vv[j]-h);
            }
        }
        __syncthreads();

        // prefetch next tile during MMA
        if (tt + 1 < 16){
            const float* A = As[(tt+1)>>3]; const float* W = Ws[(tt+1)>>3];
            int k0 = ((tt+1)&7)*128;
            #pragma unroll
            for (int i=0;i<8;i++){
                int q = tid + i*256; int m = q>>5, c4 = q&31;
                va[i] = *(const float4*)(A + (size_t)m*Hc + k0 + c4*4);
            }
            #pragma unroll
            for (int i=0;i<4;i++){
                int q = tid + i*256; int k = q>>3, ng = q&7;
                int gcol = (ng>>1)*1024 + u0 + (ng&1)*4;
                vb[i] = *(const float4*)(W + (size_t)(k0+k)*Gc + gcol);
            }
        }

        #pragma unroll
        for (int k8=0;k8<16;k8++){
            unsigned ah[2][4], al[2][4], bh[2], bl[2];
            #pragma unroll
            for (int mi=0;mi<2;mi++){
                int r = wM*32 + mi*16 + grp;
                float4 p0 = sA[r*APITCH + k8*4 + tg];
                float4 p1 = sA[(r+8)*APITCH + k8*4 + tg];
                ah[mi][0]=__float_as_uint(p0.x); ah[mi][1]=__float_as_uint(p1.x);
                ah[mi][2]=__float_as_uint(p0.z); ah[mi][3]=__float_as_uint(p1.z);
                al[mi][0]=__float_as_uint(p0.y); al[mi][1]=__float_as_uint(p1.y);
                al[mi][2]=__float_as_uint(p0.w); al[mi][3]=__float_as_uint(p1.w);
            }
            float4 q4 = sB[(wN*8+grp)*APITCH + k8*4 + tg];
            bh[0]=__float_as_uint(q4.x); bh[1]=__float_as_uint(q4.z);
            bl[0]=__float_as_uint(q4.y); bl[1]=__float_as_uint(q4.w);
            #pragma unroll
            for (int mi=0;mi<2;mi++){
                mma8(acc[mi], ah[mi], bh);
                mma8(acc[mi], ah[mi], bl);
                mma8(acc[mi], al[mi], bh);
            }
        }
        __syncthreads();
    }

    // z tile -> smem, then fused gates
    #pragma unroll
    for (int mi=0;mi<2;mi++){
        #pragma unroll
        for (int r=0;r<2;r++){
            int m = wM*32 + mi*16 + grp + 8*r, col = wN*8 + 2*tg;
            sE[m*33+col]   = acc[mi][2*r];
            sE[m*33+col+1] = acc[mi][2*r+1];
        }
    }
    __syncthreads();
    #pragma unroll
    for (int i=0;i<2;i++){
        int q = tid + i*256; int j = q&7, m = q>>3;
        int gidx = m*Hc + u0 + j;
        float zi,zf,zg_,zo;
        if (zinit){
            const float* zr = zinit + (size_t)m*Gc + u0 + j;
            zi  = sE[m*33+j]    + zr[0];
            zf  = sE[m*33+8+j]  + zr[1024];
            zg_ = sE[m*33+16+j] + zr[2048];
            zo  = sE[m*33+24+j] + zr[3072];
        } else {
            const float* br = bias + u0 + j;
            zi  = sE[m*33+j]    + br[0];
            zf  = sE[m*33+8+j]  + br[1024];
            zg_ = sE[m*33+16+j] + br[2048];
            zo  = sE[m*33+24+j] + br[3072];
        }
        float cn = sigm(zf)*cst[gidx] + sigm(zi)*tanhf(zg_);
        float hn = sigm(zo)*tanhf(cn);
        cst[gidx]=cn; hout[gidx]=hn;
        if (h4row) h4row[gidx]=hn;
    }
}

// ---------------- row softmax over V=32000, in place -------------------------
__global__ void __launch_bounds__(256) k_softmax(float* __restrict__ out)
{
    const int row = blockIdx.x;
    float* p = out + (size_t)row*Vc;
    const int tid = threadIdx.x;
    __shared__ float red[8];

    float mx = -3.4e38f;
    for (int i=tid;i<Vc;i+=256) mx = fmaxf(mx, p[i]);
    #pragma unroll
    for (int o=16;o>0;o>>=1) mx = fmaxf(mx, __shfl_xor_sync(0xffffffffu,mx,o));
    if ((tid&31)==0) red[tid>>5]=mx;
    __syncthreads();
    mx = red[0];
    #pragma unroll
    for (int j=1;j<8;j++) mx = fmaxf(mx, red[j]);

    float sum = 0.f;
    for (int i=tid;i<Vc;i+=256){ float e=__expf(p[i]-mx); p[i]=e; sum+=e; }
    #pragma unroll
    for (int o=16;o>0;o>>=1) sum += __shfl_xor_sync(0xffffffffu,sum,o);
    __syncthreads();
    if ((tid&31)==0) red[tid>>5]=sum;
    __syncthreads();
    sum = red[0];
    #pragma unroll
    for (int j=1;j<8;j++) sum += red[j];
    float inv = 1.f/sum;
    for (int i=tid;i<Vc;i+=256) p[i]*=inv;
}

// ---------------- launch -----------------------------------------------------
extern "C" void kernel_launch(void* const* d_in, const int* in_sizes, int n_in,
                              void* d_out, int out_size)
{
    const int*   tgt = (const int*)  d_in[0];
    const float* h1  = (const float*)d_in[1],  *c1 = (const float*)d_in[2];
    const float* h2  = (const float*)d_in[3],  *c2 = (const float*)d_in[4];
    const float* h3  = (const float*)d_in[5],  *c3 = (const float*)d_in[6];
    const float* h4  = (const float*)d_in[7],  *c4 = (const float*)d_in[8];
    const float* emb = (const float*)d_in[9];
    const float* W1  = (const float*)d_in[10], *U1 = (const float*)d_in[11], *b1 = (const float*)d_in[12];
    const float* W2  = (const float*)d_in[13], *U2 = (const float*)d_in[14], *b2 = (const float*)d_in[15];
    const float* W3  = (const float*)d_in[16], *U3 = (const float*)d_in[17], *b3 = (const float*)d_in[18];
    const float* W4  = (const float*)d_in[19], *U4 = (const float*)d_in[20], *b4 = (const float*)d_in[21];
    const float* Wfc = (const float*)d_in[22], *bfc = (const float*)d_in[23];
    float* out = (float*)d_out;

    float *pX,*pZ1,*phb,*pcb,*pH4;
    cudaGetSymbolAddress((void**)&pX,  g_X);
    cudaGetSymbolAddress((void**)&pZ1, g_Z1);
    cudaGetSymbolAddress((void**)&phb, g_h);
    cudaGetSymbolAddress((void**)&pcb, g_c);
    cudaGetSymbolAddress((void**)&pH4, g_H4);
    cudaFuncSetAttribute(k_cell, cudaFuncAttributeMaxDynamicSharedMemorySize, CELL_SMEM);

    const int S = Bc*Hc;
    k_init <<<S/256, 256>>>(h1,c1,h2,c2,h3,c3,h4,c4, phb, pcb);
    k_embed<<<Tc*Bc*Ec/4/256, 256>>>(tgt, emb, pX);
    // grid: (M/128 fast, N/128 slow) so W tiles are shared by resident blocks
    k_gemm<0><<<dim3((Tc*Bc)/128, Gc/128), 256>>>(pX, W1, b1, pZ1, Gc, Ec);

    const float* Wl[4] = {nullptr, W2, W3, W4};
    const float* Ul[4] = {U1, U2, U3, U4};
    const float* bl[4] = {nullptr, b2, b3, b4};

    for (int t = 0; t < Tc; t++) {
        int pr = t & 1, pw = 1 - pr;
        k_cell<<<128,256,CELL_SMEM>>>(nullptr, nullptr,
                                      phb + (0*2+pr)*S, Ul[0],
                                      pZ1 + (size_t)t*Bc*Gc, nullptr,
                                      pcb + 0*S, phb + (0*2+pw)*S, nullptr);
        for (int l = 1; l < 4; l++) {
            k_cell<<<128,256,CELL_SMEM>>>(phb + ((l-1)*2+pw)*S, Wl[l],
                                          phb + (l*2+pr)*S,     Ul[l],
                                          nullptr, bl[l],
                                          pcb + l*S, phb + (l*2+pw)*S,
                                          (l==3) ? (pH4 + (size_t)t*S) : nullptr);
        }
    }

    k_gemm<1><<<dim3((Tc*Bc)/128, Vc/128), 256>>>(pH4, Wfc, bfc, out, Vc, Hc);
    k_softmax<<<Tc*Bc, 256>>>(out);
}